// round 10
// baseline (speedup 1.0000x reference)
#include <cuda_runtime.h>
#include <cuda_bf16.h>
#include <cstdint>
#include <math.h>

// ---------------------------------------------------------------------------
// Problem constants
// ---------------------------------------------------------------------------
#define K_TOT 8192      // N_T * BS rows
#define D     128
#define NBLK  128       // grid of main kernel (64 rows each)
#define NCHUNK 64       // 8192 / 128 column chunks
#define KPOS  24576.0f  // N*(N-1)*BS
#define SCALE_F 1.69864368f   // sqrt(2 * log2(e));  acc = log2e * sim
#define LN2F   0.693147181f

// Smem layout (bytes): fp8 tiles are half-size vs bf16
#define SM_B0   0
#define SM_B1   16384
#define SM_A    32768          // 64 rows x 128B = 8KB
#define SM_POS  40960          // 64 x 4 floats
#define SM_SS   41984          // 64 x 4 floats
#define SM_RED  43008          // 8 floats
#define SM_TOTAL 43040

// Scratch: e4m3 normalized rows
__device__ __align__(16) unsigned char g_sn8[K_TOT * D];
__device__ float g_partial[NBLK];

// ---------------------------------------------------------------------------
// PTX helpers
// ---------------------------------------------------------------------------
__device__ __forceinline__ float ex2f(float x) {
    float r; asm("ex2.approx.f32 %0, %1;" : "=f"(r) : "f"(x)); return r;
}

#define CP16(dst, src) \
    asm volatile("cp.async.cg.shared.global [%0], [%1], 16;\n" :: "r"(dst), "l"(src))
#define CPCOMMIT() asm volatile("cp.async.commit_group;\n")
#define CPWAIT1()  asm volatile("cp.async.wait_group 1;\n")
#define CPWAIT0()  asm volatile("cp.async.wait_group 0;\n")

#define LDSM4(R0,R1,R2,R3,ADDR) \
    asm volatile("ldmatrix.sync.aligned.m8n8.x4.shared.b16 {%0,%1,%2,%3}, [%4];\n" \
        : "=r"(R0),"=r"(R1),"=r"(R2),"=r"(R3) : "r"(ADDR))

// m16n8k32 e4m3 x e4m3 -> f32
#define MMAFP8(D0,D1,D2,D3,A0,A1,A2,A3,B0,B1) \
    asm volatile("mma.sync.aligned.m16n8k32.row.col.f32.e4m3.e4m3.f32 " \
        "{%0,%1,%2,%3}, {%4,%5,%6,%7}, {%8,%9}, {%0,%1,%2,%3};\n" \
        : "+f"(D0),"+f"(D1),"+f"(D2),"+f"(D3) \
        : "r"(A0),"r"(A1),"r"(A2),"r"(A3),"r"(B0),"r"(B1))

// ---------------------------------------------------------------------------
// Kernel 1: row L2-normalize, pre-scale by sqrt(2*log2e), emit e4m3.
// One warp per row; each lane packs 4 consecutive elements into 4 bytes.
// ---------------------------------------------------------------------------
__global__ void normalize_kernel(const float* __restrict__ z) {
    int gw = (blockIdx.x * blockDim.x + threadIdx.x) >> 5;
    int lane = threadIdx.x & 31;
    float4 v = ((const float4*)(z + (size_t)gw * D))[lane];
    float ss = v.x*v.x + v.y*v.y + v.z*v.z + v.w*v.w;
    #pragma unroll
    for (int off = 16; off; off >>= 1)
        ss += __shfl_xor_sync(0xffffffffu, ss, off);
    float inv = SCALE_F / fmaxf(sqrtf(ss), 1e-8f);
    float x0 = v.x * inv, x1 = v.y * inv, x2 = v.z * inv, x3 = v.w * inv;
    unsigned int packed;
    asm("{\n\t.reg .b16 lo, hi;\n\t"
        "cvt.rn.satfinite.e4m3x2.f32 lo, %2, %1;\n\t"   // lo = {cvt(x1), cvt(x0)}
        "cvt.rn.satfinite.e4m3x2.f32 hi, %4, %3;\n\t"   // hi = {cvt(x3), cvt(x2)}
        "mov.b32 %0, {lo, hi};\n\t}"
        : "=r"(packed) : "f"(x0), "f"(x1), "f"(x2), "f"(x3));
    *(unsigned int*)(g_sn8 + (size_t)gw * D + lane * 4) = packed;
}

// ---------------------------------------------------------------------------
// B chunk loader: 128 cols x 128 k e4m3 (16KB), 16B-chunk XOR swizzle.
// 1024 16B transfers over 256 threads.
// ---------------------------------------------------------------------------
__device__ __forceinline__ void load_B(uint32_t sb, int buf, int chunk, int t) {
    const char* gB = (const char*)g_sn8 + (size_t)chunk * 128 * 128;
    uint32_t base = sb + (buf ? SM_B1 : SM_B0);
    #pragma unroll
    for (int it = 0; it < 4; ++it) {
        int f = t + 256 * it;          // 0..1023
        int j = f >> 3, c = f & 7;
        uint32_t dst = base + j * 128 + ((c ^ (j & 7)) << 4);
        CP16(dst, gB + j * 128 + c * 16);
    }
}

// ---------------------------------------------------------------------------
// MMA step for one 128-col chunk (4 k-steps of k32), with the ex2 epilogue of
// the PREVIOUS chunk interleaved (8 ex2 per k-step into the tensor shadow).
// ---------------------------------------------------------------------------
template<bool DOEPI>
__device__ __forceinline__ void mma_step(
    uint32_t Bb, const uint32_t (&af)[2][4][4],
    float (&accC)[2][4][4], float (&accP)[2][4][4],
    float (&Ssum)[4], int lane, int wc)
{
    #pragma unroll
    for (int mt = 0; mt < 2; ++mt)
        #pragma unroll
        for (int nt = 0; nt < 4; ++nt)
            #pragma unroll
            for (int e = 0; e < 4; ++e) accC[mt][nt][e] = 0.f;

    #pragma unroll
    for (int ks = 0; ks < 4; ++ks) {
        #pragma unroll
        for (int ntp = 0; ntp < 2; ++ntp) {
            int colr = wc * 32 + ntp * 16 + (lane & 15);
            uint32_t addr = Bb + colr * 128 +
                            (((ks * 2 + (lane >> 4)) ^ (colr & 7)) << 4);
            uint32_t b0, b1, b2, b3;
            LDSM4(b0, b1, b2, b3, addr);
            // (b0,b2) = cols 0-7 {k0-15, k16-31}; (b1,b3) = cols 8-15
            MMAFP8(accC[0][2*ntp][0], accC[0][2*ntp][1], accC[0][2*ntp][2], accC[0][2*ntp][3],
                   af[0][ks][0], af[0][ks][1], af[0][ks][2], af[0][ks][3], b0, b2);
            MMAFP8(accC[1][2*ntp][0], accC[1][2*ntp][1], accC[1][2*ntp][2], accC[1][2*ntp][3],
                   af[1][ks][0], af[1][ks][1], af[1][ks][2], af[1][ks][3], b0, b2);
            MMAFP8(accC[0][2*ntp+1][0], accC[0][2*ntp+1][1], accC[0][2*ntp+1][2], accC[0][2*ntp+1][3],
                   af[0][ks][0], af[0][ks][1], af[0][ks][2], af[0][ks][3], b1, b3);
            MMAFP8(accC[1][2*ntp+1][0], accC[1][2*ntp+1][1], accC[1][2*ntp+1][2], accC[1][2*ntp+1][3],
                   af[1][ks][0], af[1][ks][1], af[1][ks][2], af[1][ks][3], b1, b3);
        }
        if (DOEPI) {
            #pragma unroll
            for (int q = 0; q < 8; ++q) {
                int f = ks * 8 + q;
                int mt = f >> 4, nt = (f >> 2) & 3, e = f & 3;
                Ssum[mt*2 + (e >> 1)] += ex2f(accP[mt][nt][e]);
            }
        }
    }
}

// Fixup for a colliding (special) chunk: undo the ex2 wrongly summed for
// j == i (mod 2048) columns and capture the positives.
__device__ __forceinline__ void fixup(
    float (&accP)[2][4][4], float* sPos, float (&Ssum)[4],
    int rb, int rwb, int cbp, int lane, int wc)
{
    #pragma unroll
    for (int mt = 0; mt < 2; ++mt)
        #pragma unroll
        for (int nt = 0; nt < 4; ++nt)
            #pragma unroll
            for (int e = 0; e < 4; ++e) {
                int i = rwb + mt * 16 + (lane >> 2) + ((e >> 1) << 3);
                int j = cbp + wc * 32 + nt * 8 + ((lane & 3) << 1) + (e & 1);
                if (((i ^ j) & 2047) == 0) {
                    float v = accP[mt][nt][e];
                    Ssum[mt*2 + (e >> 1)] -= ex2f(v);
                    if (i != j) sPos[(i - rb) * 4 + (j >> 11)] = v;
                }
            }
}

// ---------------------------------------------------------------------------
// Kernel 2: FP8 MMA simmat + pipelined exp2 accumulation.
// 128 blocks x 256 threads (8 warps). Warp grid 2x4: wr = w>>2 (32-row half),
// wc = w&3 (32-col group). A fragments register-resident (32 regs).
// ---------------------------------------------------------------------------
__global__ void __launch_bounds__(256) clblock_mma_kernel() {
    extern __shared__ char smem[];
    float* sPos = (float*)(smem + SM_POS);   // [64][4]
    float* sS   = (float*)(smem + SM_SS);    // [64][4]
    float* sRed = (float*)(smem + SM_RED);   // [8]

    const int t = threadIdx.x, lane = t & 31, w = t >> 5;
    const int wr = w >> 2, wc = w & 3;
    const int rb = blockIdx.x * 64;
    const int rwb = rb + wr * 32;
    uint32_t sb = (uint32_t)__cvta_generic_to_shared(smem);

    // ---- async load A tile (64x128 e4m3 = 8KB) + B chunks 0,1 ----
    {
        const char* gA = (const char*)(g_sn8 + (size_t)rb * D);
        #pragma unroll
        for (int it = 0; it < 2; ++it) {
            int f = t + 256 * it;      // 0..511
            int r = f >> 3, c = f & 7;
            CP16(sb + SM_A + r * 128 + ((c ^ (r & 7)) << 4), gA + r * 128 + c * 16);
        }
        load_B(sb, 0, 0, t);
    }
    CPCOMMIT();
    load_B(sb, 1, 1, t);
    CPCOMMIT();
    CPWAIT1();              // group0 (A + chunk0) complete
    __syncthreads();

    // ---- A fragments: 2 m-tiles x 4 k-steps x 4 regs, resident ----
    uint32_t af[2][4][4];
    #pragma unroll
    for (int mt = 0; mt < 2; ++mt) {
        int row = wr * 32 + mt * 16 + (lane & 15);
        uint32_t rbase = sb + SM_A + row * 128;
        #pragma unroll
        for (int ks = 0; ks < 4; ++ks) {
            uint32_t addr = rbase + (((ks * 2 + (lane >> 4)) ^ (row & 7)) << 4);
            LDSM4(af[mt][ks][0], af[mt][ks][1], af[mt][ks][2], af[mt][ks][3], addr);
        }
    }

    float Ssum[4] = {0.f, 0.f, 0.f, 0.f};
    float accA[2][4][4], accB[2][4][4];

    // special(ch): this warp sees colliding columns in chunk ch
    #define SPEC(cb_) ((((rwb ^ (cb_)) & 0x780) == 0) && (((rwb >> 5) & 3) == wc))

    #define SYNC_LOAD(ch_) do { \
        __syncthreads(); \
        if ((ch_) + 2 < NCHUNK) { \
            load_B(sb, (ch_) & 1, (ch_) + 2, t); \
            CPCOMMIT(); \
            CPWAIT1(); \
        } else if ((ch_) + 1 < NCHUNK) { \
            CPWAIT0(); \
        } \
        __syncthreads(); \
    } while (0)

    // ---- peeled ch = 0 (no previous epilogue) ----
    mma_step<false>(sb + SM_B0, af, accA, accB, Ssum, lane, wc);
    SYNC_LOAD(0);
    // ---- peeled ch = 1 (epilogue of ch 0 from accA) ----
    mma_step<true>(sb + SM_B1, af, accB, accA, Ssum, lane, wc);
    if (SPEC(0)) fixup(accA, sPos, Ssum, rb, rwb, 0, lane, wc);
    SYNC_LOAD(1);

    for (int p = 1; p < 32; ++p) {
        const int ch0 = 2 * p;
        mma_step<true>(sb + SM_B0, af, accA, accB, Ssum, lane, wc);
        if (SPEC((ch0 - 1) * 128))
            fixup(accB, sPos, Ssum, rb, rwb, (ch0 - 1) * 128, lane, wc);
        SYNC_LOAD(ch0);

        mma_step<true>(sb + SM_B1, af, accB, accA, Ssum, lane, wc);
        if (SPEC(ch0 * 128))
            fixup(accA, sPos, Ssum, rb, rwb, ch0 * 128, lane, wc);
        SYNC_LOAD(ch0 + 1);
    }

    // ---- final epilogue: chunk 63 lives in accB ----
    #pragma unroll
    for (int f = 0; f < 32; ++f) {
        int mt = f >> 4, nt = (f >> 2) & 3, e = f & 3;
        Ssum[mt*2 + (e >> 1)] += ex2f(accB[mt][nt][e]);
    }
    if (SPEC(63 * 128)) fixup(accB, sPos, Ssum, rb, rwb, 63 * 128, lane, wc);

    // ---- per-row partials: quad-reduce, write per (row, col-group) ----
    #pragma unroll
    for (int s = 0; s < 4; ++s) {
        Ssum[s] += __shfl_xor_sync(0xffffffffu, Ssum[s], 1);
        Ssum[s] += __shfl_xor_sync(0xffffffffu, Ssum[s], 2);
    }
    if ((lane & 3) == 0) {
        int g = lane >> 2;
        #pragma unroll
        for (int s = 0; s < 4; ++s) {
            int lrow = wr * 32 + (s >> 1) * 16 + g + (s & 1) * 8;
            sS[lrow * 4 + wc] = Ssum[s];
        }
    }
    __syncthreads();

    // ---- per-row loss: lse - pos over the 3 positives ----
    float contrib = 0.f;
    if (t < 64) {
        int myq = rb >> 11;
        float S0 = sS[t * 4] + sS[t * 4 + 1] + sS[t * 4 + 2] + sS[t * 4 + 3];
        #pragma unroll
        for (int qq = 0; qq < 4; ++qq) {
            if (qq == myq) continue;
            float ap = sPos[t * 4 + qq];          // = log2e * sim_pos
            contrib += logf(exp2f(ap) + S0) - ap * LN2F;
        }
    }
    #pragma unroll
    for (int off = 16; off; off >>= 1)
        contrib += __shfl_xor_sync(0xffffffffu, contrib, off);
    if (lane == 0) sRed[w] = contrib;
    __syncthreads();
    if (t == 0) {
        float s = 0.f;
        #pragma unroll
        for (int k = 0; k < 8; ++k) s += sRed[k];
        g_partial[blockIdx.x] = s;
    }
}

// ---------------------------------------------------------------------------
// Kernel 3: final deterministic reduction.
// ---------------------------------------------------------------------------
__global__ void final_kernel(float* __restrict__ out) {
    __shared__ float sh[4];
    int t = threadIdx.x;
    float v = g_partial[t];
    #pragma unroll
    for (int off = 16; off; off >>= 1)
        v += __shfl_xor_sync(0xffffffffu, v, off);
    if ((t & 31) == 0) sh[t >> 5] = v;
    __syncthreads();
    if (t == 0) out[0] = (sh[0] + sh[1] + sh[2] + sh[3]) / KPOS;
}

// ---------------------------------------------------------------------------
extern "C" void kernel_launch(void* const* d_in, const int* in_sizes, int n_in,
                              void* d_out, int out_size) {
    const float* z = (const float*)d_in[0];
    float* out = (float*)d_out;

    cudaFuncSetAttribute(clblock_mma_kernel,
                         cudaFuncAttributeMaxDynamicSharedMemorySize, SM_TOTAL);

    normalize_kernel<<<K_TOT / 8, 256>>>(z);
    clblock_mma_kernel<<<NBLK, 256, SM_TOTAL>>>();
    final_kernel<<<1, 128>>>(out);
}

// round 12
// speedup vs baseline: 1.6152x; 1.6152x over previous
#include <cuda_runtime.h>
#include <cuda_bf16.h>
#include <cstdint>
#include <math.h>

// ---------------------------------------------------------------------------
// Problem constants
// ---------------------------------------------------------------------------
#define K_TOT 8192      // N_T * BS rows
#define D     128
#define NTILE_TOT 2080  // 64*65/2 upper-triangle 128x128 tiles
#define KPOS  24576.0f
#define SCALE_F 1.69864368f   // sqrt(2 * log2(e));  acc = log2e * sim
#define LN2F   0.693147181f

// Smem layout (bytes)
#define SM_A    0              // 128 rows x 256B = 32KB
#define SM_B0   32768
#define SM_B1   65536
#define SM_ROW  98304          // 128 x 2 floats
#define SM_COL  99328          // 128 x 4 floats
#define SM_TOTAL 101376

// Scratch
__device__ __align__(16) __nv_bfloat16 g_snb[K_TOT * D];
__device__ float g_Srow[NTILE_TOT * 128];
__device__ float g_Scol[NTILE_TOT * 128];
__device__ float g_pos[K_TOT * 4];
__device__ float g_part[32];

// ---------------------------------------------------------------------------
// PTX helpers
// ---------------------------------------------------------------------------
__device__ __forceinline__ float ex2f(float x) {
    float r; asm("ex2.approx.f32 %0, %1;" : "=f"(r) : "f"(x)); return r;
}

#define CP16(dst, src) \
    asm volatile("cp.async.cg.shared.global [%0], [%1], 16;\n" :: "r"(dst), "l"(src))
#define CPCOMMIT() asm volatile("cp.async.commit_group;\n")
#define CPWAIT1()  asm volatile("cp.async.wait_group 1;\n")
#define CPWAIT0()  asm volatile("cp.async.wait_group 0;\n")

#define LDSM4(R0,R1,R2,R3,ADDR) \
    asm volatile("ldmatrix.sync.aligned.m8n8.x4.shared.b16 {%0,%1,%2,%3}, [%4];\n" \
        : "=r"(R0),"=r"(R1),"=r"(R2),"=r"(R3) : "r"(ADDR))

#define MMA16816(D0,D1,D2,D3,A0,A1,A2,A3,B0,B1) \
    asm volatile("mma.sync.aligned.m16n8k16.row.col.f32.bf16.bf16.f32 " \
        "{%0,%1,%2,%3}, {%4,%5,%6,%7}, {%8,%9}, {%0,%1,%2,%3};\n" \
        : "+f"(D0),"+f"(D1),"+f"(D2),"+f"(D3) \
        : "r"(A0),"r"(A1),"r"(A2),"r"(A3),"r"(B0),"r"(B1))

// ---------------------------------------------------------------------------
// Kernel 1: row L2-normalize, pre-scale by sqrt(2*log2e), emit bf16.
// ---------------------------------------------------------------------------
__global__ void normalize_kernel(const float* __restrict__ z) {
    int gw = (blockIdx.x * blockDim.x + threadIdx.x) >> 5;
    int lane = threadIdx.x & 31;
    float4 v = ((const float4*)(z + (size_t)gw * D))[lane];
    float ss = v.x*v.x + v.y*v.y + v.z*v.z + v.w*v.w;
    #pragma unroll
    for (int off = 16; off; off >>= 1)
        ss += __shfl_xor_sync(0xffffffffu, ss, off);
    float inv = SCALE_F / fmaxf(sqrtf(ss), 1e-8f);
    __nv_bfloat162 p0 = __floats2bfloat162_rn(v.x * inv, v.y * inv);
    __nv_bfloat162 p1 = __floats2bfloat162_rn(v.z * inv, v.w * inv);
    uint2 o;
    o.x = *(unsigned int*)&p0;
    o.y = *(unsigned int*)&p1;
    *(uint2*)(g_snb + (size_t)gw * D + lane * 4) = o;
}

// ---------------------------------------------------------------------------
// 128-row x 128-k bf16 tile loader (32KB), 16B-chunk XOR swizzle. 256 threads.
// ---------------------------------------------------------------------------
__device__ __forceinline__ void load_tile(uint32_t dstbase,
                                          const __nv_bfloat16* src, int t) {
    #pragma unroll
    for (int it = 0; it < 8; ++it) {
        int f = t + 256 * it;          // 0..2047
        int j = f >> 4, c = f & 15;
        uint32_t dst = dstbase + j * 256 + ((c ^ (j & 7)) << 4);
        CP16(dst, (const char*)src + j * 256 + c * 16);
    }
}

// ---------------------------------------------------------------------------
// Kernel 2: symmetric (upper-triangle) HMMA simmat + exp2 row/col sums.
// 128 CTAs x 256 threads. CTA (k = b>>2, s = b&3) handles a 16/17-tile
// segment of chain k = [rows k sweep J=k..63] + [rows 63-k sweep].
// Warp grid 4x2: wr = w>>1 (32-row group), wc = w&1 (64-col half).
// ---------------------------------------------------------------------------
__global__ void __launch_bounds__(256, 1) clblock_mma_kernel() {
    extern __shared__ char smem[];
    float* sRow = (float*)(smem + SM_ROW);   // [128][2]
    float* sCol = (float*)(smem + SM_COL);   // [128][4]

    const int t = threadIdx.x, lane = t & 31, w = t >> 5;
    const int wr = w >> 1, wc = w & 1;
    const int k = blockIdx.x >> 2, s = blockIdx.x & 3;
    const int s0 = s ? (17 + 16 * (s - 1)) : 0;
    const int lastLt = s0 + (s ? 16 : 17) - 1;
    uint32_t sb = (uint32_t)__cvta_generic_to_shared(smem);

    #define TILE_I(tt) (((tt) < 64 - k) ? k : (63 - k))
    #define TILE_J(tt) (((tt) < 64 - k) ? (k + (tt)) : ((63 - k) + ((tt) - (64 - k))))

    // ---- prologue: A(I0), B(s0), B(s0+1) ----
    int curI = TILE_I(s0);
    load_tile(sb + SM_A, g_snb + (size_t)curI * 128 * D, t);
    load_tile(sb + ((s0 & 1) ? SM_B1 : SM_B0),
              g_snb + (size_t)TILE_J(s0) * 128 * D, t);
    CPCOMMIT();
    if (s0 + 1 <= lastLt) {
        load_tile(sb + (((s0 + 1) & 1) ? SM_B1 : SM_B0),
                  g_snb + (size_t)TILE_J(s0 + 1) * 128 * D, t);
        CPCOMMIT();
    }
    bool needA = true;
    uint32_t af[2][8][4];

    for (int lt = s0; lt <= lastLt; ++lt) {
        const int I = TILE_I(lt), J = TILE_J(lt);
        if (lt == lastLt) { CPWAIT0(); } else { CPWAIT1(); }
        if (I != curI) {                       // at most once per CTA
            load_tile(sb + SM_A, g_snb + (size_t)I * 128 * D, t);
            CPCOMMIT(); CPWAIT0();
            curI = I; needA = true;
        }
        __syncthreads();
        if (needA) {                           // (re)load A fragments
            #pragma unroll
            for (int mt = 0; mt < 2; ++mt) {
                int row = wr * 32 + mt * 16 + (lane & 15);
                uint32_t rbase = sb + SM_A + row * 256;
                #pragma unroll
                for (int ks = 0; ks < 8; ++ks) {
                    uint32_t addr = rbase + (((ks * 2 + (lane >> 4)) ^ (row & 7)) << 4);
                    LDSM4(af[mt][ks][0], af[mt][ks][1], af[mt][ks][2], af[mt][ks][3], addr);
                }
            }
            needA = false;
        }

        const uint32_t Bb = sb + ((lt & 1) ? SM_B1 : SM_B0);
        float acc[2][8][4];
        #pragma unroll
        for (int mt = 0; mt < 2; ++mt)
            #pragma unroll
            for (int nt = 0; nt < 8; ++nt)
                #pragma unroll
                for (int e = 0; e < 4; ++e) acc[mt][nt][e] = 0.f;

        #pragma unroll
        for (int ks = 0; ks < 8; ++ks) {
            #pragma unroll
            for (int ntp = 0; ntp < 4; ++ntp) {
                int colr = wc * 64 + ntp * 16 + (lane & 15);
                uint32_t addr = Bb + colr * 256 +
                                (((ks * 2 + (lane >> 4)) ^ (colr & 7)) << 4);
                uint32_t b0, b1, b2, b3;
                LDSM4(b0, b1, b2, b3, addr);
                MMA16816(acc[0][2*ntp][0], acc[0][2*ntp][1], acc[0][2*ntp][2], acc[0][2*ntp][3],
                         af[0][ks][0], af[0][ks][1], af[0][ks][2], af[0][ks][3], b0, b2);
                MMA16816(acc[1][2*ntp][0], acc[1][2*ntp][1], acc[1][2*ntp][2], acc[1][2*ntp][3],
                         af[1][ks][0], af[1][ks][1], af[1][ks][2], af[1][ks][3], b0, b2);
                MMA16816(acc[0][2*ntp+1][0], acc[0][2*ntp+1][1], acc[0][2*ntp+1][2], acc[0][2*ntp+1][3],
                         af[0][ks][0], af[0][ks][1], af[0][ks][2], af[0][ks][3], b1, b3);
                MMA16816(acc[1][2*ntp+1][0], acc[1][2*ntp+1][1], acc[1][2*ntp+1][2], acc[1][2*ntp+1][3],
                         af[1][ks][0], af[1][ks][1], af[1][ks][2], af[1][ks][3], b1, b3);
            }
        }

        // ---- epilogue: ex2 once per element -> row sums AND col sums ----
        float Ssum[4] = {0.f, 0.f, 0.f, 0.f};
        float colacc[16];
        #pragma unroll
        for (int c16 = 0; c16 < 16; ++c16) colacc[c16] = 0.f;
        #pragma unroll
        for (int mt = 0; mt < 2; ++mt)
            #pragma unroll
            for (int nt = 0; nt < 8; ++nt)
                #pragma unroll
                for (int e = 0; e < 4; ++e) {
                    float x = ex2f(acc[mt][nt][e]);
                    Ssum[mt*2 + (e >> 1)] += x;
                    colacc[nt*2 + (e & 1)] += x;
                }

        // collisions (j == i mod 2048) iff (J-I)%16==0, at local row==col
        if (((J - I) & 15) == 0) {
            #pragma unroll
            for (int mt = 0; mt < 2; ++mt)
                #pragma unroll
                for (int nt = 0; nt < 8; ++nt)
                    #pragma unroll
                    for (int e = 0; e < 4; ++e) {
                        int rl = wr*32 + mt*16 + (lane >> 2) + ((e >> 1) << 3);
                        int cl = wc*64 + nt*8 + ((lane & 3) << 1) + (e & 1);
                        if (rl == cl) {
                            float v = acc[mt][nt][e];
                            float x = ex2f(v);
                            Ssum[mt*2 + (e >> 1)] -= x;
                            colacc[nt*2 + (e & 1)] -= x;
                            if (I != J) {       // positive pair, both directions
                                int gi = I*128 + rl, gj = J*128 + cl;
                                g_pos[gi*4 + (J >> 4)] = v;
                                g_pos[gj*4 + (I >> 4)] = v;
                            }
                        }
                    }
        }

        // ---- row partials: quad-reduce, stage [128][2] ----
        #pragma unroll
        for (int s4 = 0; s4 < 4; ++s4) {
            Ssum[s4] += __shfl_xor_sync(0xffffffffu, Ssum[s4], 1);
            Ssum[s4] += __shfl_xor_sync(0xffffffffu, Ssum[s4], 2);
        }
        if ((lane & 3) == 0) {
            #pragma unroll
            for (int s4 = 0; s4 < 4; ++s4) {
                int lrow = wr*32 + (s4 >> 1)*16 + (lane >> 2) + (s4 & 1)*8;
                sRow[lrow*2 + wc] = Ssum[s4];
            }
        }
        // ---- col partials: reduce over lanes sharing lane&3, stage [128][4] ----
        #pragma unroll
        for (int c16 = 0; c16 < 16; ++c16) {
            colacc[c16] += __shfl_xor_sync(0xffffffffu, colacc[c16], 4);
            colacc[c16] += __shfl_xor_sync(0xffffffffu, colacc[c16], 8);
            colacc[c16] += __shfl_xor_sync(0xffffffffu, colacc[c16], 16);
        }
        if (lane < 4) {
            #pragma unroll
            for (int c16 = 0; c16 < 16; ++c16) {
                int cl = wc*64 + (c16 >> 1)*8 + lane*2 + (c16 & 1);
                sCol[cl*4 + wr] = colacc[c16];
            }
        }
        __syncthreads();    // staging done; B buffer free

        const int tid = I*64 - (I*(I - 1))/2 + (J - I);
        if (t < 128) {
            g_Srow[tid*128 + t] = sRow[t*2] + sRow[t*2 + 1];
        } else {
            int r = t - 128;
            g_Scol[tid*128 + r] = sCol[r*4] + sCol[r*4+1] + sCol[r*4+2] + sCol[r*4+3];
        }

        if (lt + 2 <= lastLt) {
            load_tile(sb + ((lt & 1) ? SM_B1 : SM_B0),
                      g_snb + (size_t)TILE_J(lt + 2) * 128 * D, t);
            CPCOMMIT();
        }
    }
    #undef TILE_I
    #undef TILE_J
}

// ---------------------------------------------------------------------------
// Kernel 3: gather per-row S0 from tile partials, per-row loss, 32 partials.
// ---------------------------------------------------------------------------
__global__ void rowloss_kernel() {
    __shared__ float sh[8];
    int i = blockIdx.x * 256 + threadIdx.x;
    int I = i >> 7, r = i & 127;
    float S0 = 0.f;
    int b = I*64 - (I*(I - 1))/2;
    for (int J = I; J < 64; ++J)
        S0 += g_Srow[(b + J - I)*128 + r];
    for (int Ip = 0; Ip < I; ++Ip) {
        int b2 = Ip*64 - (Ip*(Ip - 1))/2;
        S0 += g_Scol[(b2 + I - Ip)*128 + r];
    }
    int myq = i >> 11;
    float c = 0.f;
    #pragma unroll
    for (int qq = 0; qq < 4; ++qq) {
        if (qq != myq) {
            float ap = g_pos[i*4 + qq];          // = log2e * sim_pos
            c += logf(exp2f(ap) + S0) - ap * LN2F;
        }
    }
    #pragma unroll
    for (int off = 16; off; off >>= 1)
        c += __shfl_xor_sync(0xffffffffu, c, off);
    if ((threadIdx.x & 31) == 0) sh[threadIdx.x >> 5] = c;
    __syncthreads();
    if (threadIdx.x == 0) {
        float ss = 0.f;
        #pragma unroll
        for (int q = 0; q < 8; ++q) ss += sh[q];
        g_part[blockIdx.x] = ss;
    }
}

// ---------------------------------------------------------------------------
// Kernel 4: final reduction of 32 partials.
// ---------------------------------------------------------------------------
__global__ void final_kernel(float* __restrict__ out) {
    int t = threadIdx.x;
    float v = g_part[t];
    #pragma unroll
    for (int off = 16; off; off >>= 1)
        v += __shfl_xor_sync(0xffffffffu, v, off);
    if (t == 0) out[0] = v / KPOS;
}

// ---------------------------------------------------------------------------
extern "C" void kernel_launch(void* const* d_in, const int* in_sizes, int n_in,
                              void* d_out, int out_size) {
    const float* z = (const float*)d_in[0];
    float* out = (float*)d_out;

    cudaFuncSetAttribute(clblock_mma_kernel,
                         cudaFuncAttributeMaxDynamicSharedMemorySize, SM_TOTAL);

    normalize_kernel<<<K_TOT / 8, 256>>>(z);
    clblock_mma_kernel<<<128, 256, SM_TOTAL>>>();
    rowloss_kernel<<<32, 256>>>();
    final_kernel<<<1, 32>>>(out);
}